// round 1
// baseline (speedup 1.0000x reference)
#include <cuda_runtime.h>
#include <math.h>

#define BS   8
#define T_   32
#define C_   64
#define NN   4096
#define KK   32
#define DD   64
#define HH   64
#define FIN  320   // 5*D

// ---------------- persistent scratch (no allocation allowed) ----------------
__device__ float g_pm[2][BS * NN * DD];   // double-buffered messages
__device__ float g_h [BS * NN * DD];      // hidden state (in-place per update)
__device__ float g_ep[BS * NN * DD];      // eff_prim
__device__ float g_ek[BS * NN * DD];      // eff_key
__device__ float g_ed[BS * NN];           // eff_decay (scalar per b,n)

__device__ __forceinline__ float sigf(float x) { return 1.f / (1.f + __expf(-x)); }

// =============================================================================
// Kernel A: modulator MLP + state init.  One CTA per neuron n, 512 threads.
// =============================================================================
__global__ void __launch_bounds__(512) modk(
    const float* __restrict__ h_in, const float* __restrict__ pm_in,
    const float* __restrict__ tp,   const float* __restrict__ tk,
    const float* __restrict__ prim, const float* __restrict__ keyp,
    const float* __restrict__ dlog, const float* __restrict__ fc1w,
    const float* __restrict__ fc1b, const float* __restrict__ fc2w,
    const float* __restrict__ fc2b, const float* __restrict__ mll)
{
    const int n   = blockIdx.x;
    const int tid = threadIdx.x;

    __shared__ __align__(16) float s_in[FIN * 12];      // [j][b] pad 12 (float4-friendly)
    __shared__ float s_part[8 * 8 * 64];                // [seg][b][h]
    __shared__ float s_x[8 * 64];                       // tanh(fc1) activations
    __shared__ float s_o[24];                           // fc2 outputs [b][3]
    __shared__ float s_norm[16];                        // [b][{prim,key}]

    // ---- stage mod_input transposed: s_in[j*12 + b] ----
    for (int idx = tid; idx < BS * FIN; idx += 512) {
        const int b = idx / FIN, j = idx % FIN;
        float v;
        if      (j <  64) v = h_in[((size_t)b * NN + n) * DD + j];
        else if (j < 128) v = tp  [((size_t)b * NN + n) * DD + j - 64];
        else if (j < 192) v = tk  [((size_t)b * NN + n) * DD + j - 128];
        else if (j < 256) v = prim[(size_t)n * DD + j - 192];
        else              v = keyp[(size_t)n * DD + j - 256];
        s_in[j * 12 + b] = v;
    }
    __syncthreads();

    // ---- fc1: thread (seg,h) covers j in [seg*40, seg*40+40) for ALL 8 batches ----
    {
        const int seg = tid >> 6, hh = tid & 63;
        float a0=0,a1=0,a2=0,a3=0,a4=0,a5=0,a6=0,a7=0;
        const float* W = fc1w + (size_t)n * FIN * HH + hh;
        const int j0 = seg * 40;
        #pragma unroll 8
        for (int jj = 0; jj < 40; jj++) {
            const int j = j0 + jj;
            const float w = W[(size_t)j * HH];
            const float4 i0 = *(const float4*)&s_in[j * 12];
            const float4 i1 = *(const float4*)&s_in[j * 12 + 4];
            a0 += w * i0.x; a1 += w * i0.y; a2 += w * i0.z; a3 += w * i0.w;
            a4 += w * i1.x; a5 += w * i1.y; a6 += w * i1.z; a7 += w * i1.w;
        }
        float acc[8] = {a0,a1,a2,a3,a4,a5,a6,a7};
        #pragma unroll
        for (int b = 0; b < 8; b++)
            s_part[(seg * 8 + b) * 64 + hh] = acc[b];
    }
    __syncthreads();

    // ---- reduce segments, bias, tanh ----
    {
        const int b = tid >> 6, h = tid & 63;
        float s = 0.f;
        #pragma unroll
        for (int seg = 0; seg < 8; seg++) s += s_part[(seg * 8 + b) * 64 + h];
        s_x[b * 64 + h] = tanhf(s + fc1b[(size_t)n * HH + h]);
    }
    __syncthreads();

    // ---- fc2 (24 threads) + trace norms (threads 32..47) ----
    if (tid < 24) {
        const int b = tid / 3, o = tid % 3;
        float acc = fc2b[(size_t)n * 3 + o];
        #pragma unroll 8
        for (int h = 0; h < 64; h++)
            acc += s_x[b * 64 + h] * fc2w[((size_t)n * 64 + h) * 3 + o];
        s_o[b * 3 + o] = acc;
    } else if (tid >= 32 && tid < 48) {
        const int q = tid - 32, b = q >> 1, which = q & 1;
        float s = 0.f;
        const int base = 64 + which * 64;
        #pragma unroll 8
        for (int d = 0; d < 64; d++) {
            const float v = s_in[(base + d) * 12 + b];
            s += v * v;
        }
        s_norm[b * 2 + which] = fmaxf(sqrtf(s), 1e-8f);
    }
    __syncthreads();

    // ---- finalize eff_* and init state ----
    {
        const int b = tid >> 6, d = tid & 63;
        const float mod_lr = sigf(mll[0]);
        const float gp = tanhf(s_o[b * 3 + 0]);
        const float gk = tanhf(s_o[b * 3 + 1]);
        const float dm = s_o[b * 3 + 2];
        const float tpv = s_in[(64 + d) * 12 + b];
        const float tkv = s_in[(128 + d) * 12 + b];
        const size_t off = ((size_t)b * NN + n) * DD + d;
        g_ep[off] = prim[(size_t)n * DD + d] + mod_lr * gp * (tpv / s_norm[b * 2 + 0]);
        g_ek[off] = keyp[(size_t)n * DD + d] + mod_lr * gk * (tkv / s_norm[b * 2 + 1]);
        g_h [off] = s_in[d * 12 + b];
        g_pm[0][off] = pm_in[off];
        if (d == 0) g_ed[(size_t)b * NN + n] = sigf(dlog[n] + dm);
    }
}

// =============================================================================
// Kernel B: one scan update.  One CTA per neuron n, 8 warps = 8 batches.
// =============================================================================
#define SMEM_B ((8 * 2080 + 2048 + 256 + 512) * 4 + 32 * 4)   // 77,952 B

__global__ void __launch_bounds__(256) stepk(
    int parity, int t0,
    const float* __restrict__ cc, const float* __restrict__ bw,
    const float* __restrict__ gw, const int* __restrict__ conn,
    float* __restrict__ out)
{
    extern __shared__ float sm[];
    float* s_msg = sm;                         // 8 * 32 * 65
    float* s_bw  = sm + 8 * 2080;              // 32 * 64  (k = nb*8+j flattened)
    float* s_gw  = s_bw + 2048;                // 4 * 64
    float* s_key = s_gw + 256;                 // 8 * 64
    int*   s_idx = (int*)(s_key + 512);        // 32

    const int n   = blockIdx.x;
    const int tid = threadIdx.x;
    const int b   = tid >> 5;
    const int l   = tid & 31;

    const float* pm_in  = g_pm[parity];
    float*       pm_out = g_pm[parity ^ 1];

    for (int i = tid; i < 2048; i += 256) s_bw[i] = bw[(size_t)n * 2048 + i];
    if (tid < 256) s_gw[tid] = gw[(size_t)n * 256 + tid];
    if (tid < 32)  s_idx[tid] = conn[(size_t)n * KK + tid];
    for (int i = tid; i < 512; i += 256) {
        const int bb = i >> 6, dd = i & 63;
        s_key[i] = g_ek[((size_t)bb * NN + n) * DD + dd];
    }
    __syncthreads();

    // ---- gather 32 neighbor messages into padded smem (conflict-free) ----
    float* M = s_msg + b * 2080;
    const float* pmb = pm_in + (size_t)b * NN * DD;
    #pragma unroll
    for (int k = 0; k < 32; k++) {
        const int src = s_idx[k];
        const float v0 = __ldg(&pmb[src * DD + l]);
        const float v1 = __ldg(&pmb[src * DD + 32 + l]);
        M[k * 65 + l]      = v0;
        M[k * 65 + 32 + l] = v1;
    }
    __syncwarp();

    // ---- sim: lane k = l computes dot(eff_key, msg_k) ----
    float sim = 0.f;
    {
        const float*  mk = M + l * 65;
        const float4* kf = (const float4*)(s_key + b * 64);
        #pragma unroll
        for (int q = 0; q < 16; q++) {
            const float4 kv = kf[q];
            sim += kv.x * mk[q*4] + kv.y * mk[q*4+1] + kv.z * mk[q*4+2] + kv.w * mk[q*4+3];
        }
    }
    const float w = sigf(sim);

    // ---- fused weighted + branch sums: lane l owns d = l and d = l+32 ----
    float acc[4][2] = {{0,0},{0,0},{0,0},{0,0}};
    #pragma unroll
    for (int k = 0; k < 32; k++) {
        const float wk = __shfl_sync(0xffffffffu, w, k);
        const float m0 = M[k * 65 + l],      m1 = M[k * 65 + 32 + l];
        const float w0 = s_bw[k * 64 + l],   w1 = s_bw[k * 64 + 32 + l];
        acc[k >> 3][0] += (wk * m0) * w0;
        acc[k >> 3][1] += (wk * m1) * w1;
    }

    // ---- branch tanh -> group sum -> group tanh (ng=1, mean = identity) ----
    float r0 = 0.f, r1 = 0.f;
    #pragma unroll
    for (int nb = 0; nb < 4; nb++) {
        r0 += tanhf(acc[nb][0]) * s_gw[nb * 64 + l];
        r1 += tanhf(acc[nb][1]) * s_gw[nb * 64 + 32 + l];
    }
    r0 = tanhf(r0);
    r1 = tanhf(r1);

    if (n < C_) {   // cc injection on first C neurons
        const size_t cco = (((size_t)b * T_ + t0) * C_ + n) * DD;
        r0 += cc[cco + l];
        r1 += cc[cco + 32 + l];
    }

    // ---- h / message update ----
    const size_t off = ((size_t)b * NN + n) * DD;
    const float ed = g_ed[(size_t)b * NN + n];
    const float h0 = g_h[off + l], h1 = g_h[off + 32 + l];
    const float nh0 = ed * h0 + (1.f - ed) * r0;
    const float nh1 = ed * h1 + (1.f - ed) * r1;
    g_h[off + l]      = nh0;
    g_h[off + 32 + l] = nh1;
    const float p0 = tanhf(nh0 * g_ep[off + l]);
    const float p1 = tanhf(nh1 * g_ep[off + 32 + l]);
    pm_out[off + l]      = p0;
    pm_out[off + 32 + l] = p1;

    if (n < C_) {   // emit the 4 timesteps this update covers
        #pragma unroll
        for (int tt = 0; tt < 4; tt++) {
            const size_t oo = (((size_t)b * T_ + t0 + tt) * C_ + n) * DD;
            out[oo + l]      = p0;
            out[oo + 32 + l] = p1;
        }
    }
}

// =============================================================================
extern "C" void kernel_launch(void* const* d_in, const int* in_sizes, int n_in,
                              void* d_out, int out_size)
{
    const float* cc    = (const float*)d_in[0];
    const float* h_in  = (const float*)d_in[1];
    const float* pm_in = (const float*)d_in[2];
    const float* tp    = (const float*)d_in[3];
    const float* tk    = (const float*)d_in[4];
    const float* prim  = (const float*)d_in[5];
    const float* keyp  = (const float*)d_in[6];
    const float* dlog  = (const float*)d_in[7];
    const float* bw    = (const float*)d_in[8];
    const float* gw    = (const float*)d_in[9];
    const float* fc1w  = (const float*)d_in[10];
    const float* fc1b  = (const float*)d_in[11];
    const float* fc2w  = (const float*)d_in[12];
    const float* fc2b  = (const float*)d_in[13];
    const float* mll   = (const float*)d_in[14];
    const int*   conn  = (const int*)d_in[15];
    float* out = (float*)d_out;

    cudaFuncSetAttribute(stepk, cudaFuncAttributeMaxDynamicSharedMemorySize, SMEM_B);

    modk<<<NN, 512>>>(h_in, pm_in, tp, tk, prim, keyp, dlog,
                      fc1w, fc1b, fc2w, fc2b, mll);

    // stride = 4 (fixed by setup): updates at t = 0,4,...,28; output replicated x4
    for (int u = 0; u < 8; u++) {
        stepk<<<NN, 256, SMEM_B>>>(u & 1, 4 * u, cc, bw, gw, conn, out);
    }
}

// round 2
// speedup vs baseline: 1.7306x; 1.7306x over previous
#include <cuda_runtime.h>
#include <math.h>

#define BS   8
#define T_   32
#define C_   64
#define NN   4096
#define KK   32
#define DD   64
#define HH   64
#define FIN  320   // 5*D

// ---------------- persistent scratch (no allocation allowed) ----------------
__device__ float g_pm[2][BS * NN * DD];   // double-buffered messages
__device__ float g_h [BS * NN * DD];      // hidden state (in-place per update)
__device__ float g_ep[BS * NN * DD];      // eff_prim
__device__ float g_ek[BS * NN * DD];      // eff_key
__device__ float g_ed[BS * NN];           // eff_decay (scalar per b,n)

__device__ __forceinline__ float sigf(float x) { return 1.f / (1.f + __expf(-x)); }

// =============================================================================
// Kernel A: modulator MLP + state init.  One CTA per neuron n, 512 threads.
// =============================================================================
__global__ void __launch_bounds__(512) modk(
    const float* __restrict__ h_in, const float* __restrict__ pm_in,
    const float* __restrict__ tp,   const float* __restrict__ tk,
    const float* __restrict__ prim, const float* __restrict__ keyp,
    const float* __restrict__ dlog, const float* __restrict__ fc1w,
    const float* __restrict__ fc1b, const float* __restrict__ fc2w,
    const float* __restrict__ fc2b, const float* __restrict__ mll)
{
    const int n   = blockIdx.x;
    const int tid = threadIdx.x;

    __shared__ __align__(16) float s_in[FIN * 12];      // [j][b] pad 12 (float4-friendly)
    __shared__ float s_part[8 * 8 * 64];                // [seg][b][h]
    __shared__ float s_x[8 * 64];                       // tanh(fc1) activations
    __shared__ float s_o[24];                           // fc2 outputs [b][3]
    __shared__ float s_norm[16];                        // [b][{prim,key}]

    // ---- stage mod_input transposed: s_in[j*12 + b] ----
    for (int idx = tid; idx < BS * FIN; idx += 512) {
        const int b = idx / FIN, j = idx % FIN;
        float v;
        if      (j <  64) v = h_in[((size_t)b * NN + n) * DD + j];
        else if (j < 128) v = tp  [((size_t)b * NN + n) * DD + j - 64];
        else if (j < 192) v = tk  [((size_t)b * NN + n) * DD + j - 128];
        else if (j < 256) v = prim[(size_t)n * DD + j - 192];
        else              v = keyp[(size_t)n * DD + j - 256];
        s_in[j * 12 + b] = v;
    }
    __syncthreads();

    // ---- fc1: thread (seg,h) covers j in [seg*40, seg*40+40) for ALL 8 batches ----
    {
        const int seg = tid >> 6, hh = tid & 63;
        float a0=0,a1=0,a2=0,a3=0,a4=0,a5=0,a6=0,a7=0;
        const float* W = fc1w + (size_t)n * FIN * HH + hh;
        const int j0 = seg * 40;
        #pragma unroll 8
        for (int jj = 0; jj < 40; jj++) {
            const int j = j0 + jj;
            const float w = W[(size_t)j * HH];
            const float4 i0 = *(const float4*)&s_in[j * 12];
            const float4 i1 = *(const float4*)&s_in[j * 12 + 4];
            a0 += w * i0.x; a1 += w * i0.y; a2 += w * i0.z; a3 += w * i0.w;
            a4 += w * i1.x; a5 += w * i1.y; a6 += w * i1.z; a7 += w * i1.w;
        }
        float acc[8] = {a0,a1,a2,a3,a4,a5,a6,a7};
        #pragma unroll
        for (int b = 0; b < 8; b++)
            s_part[(seg * 8 + b) * 64 + hh] = acc[b];
    }
    __syncthreads();

    // ---- reduce segments, bias, tanh ----
    {
        const int b = tid >> 6, h = tid & 63;
        float s = 0.f;
        #pragma unroll
        for (int seg = 0; seg < 8; seg++) s += s_part[(seg * 8 + b) * 64 + h];
        s_x[b * 64 + h] = tanhf(s + fc1b[(size_t)n * HH + h]);
    }
    __syncthreads();

    // ---- fc2 (24 threads) + trace norms (threads 32..47) ----
    if (tid < 24) {
        const int b = tid / 3, o = tid % 3;
        float acc = fc2b[(size_t)n * 3 + o];
        #pragma unroll 8
        for (int h = 0; h < 64; h++)
            acc += s_x[b * 64 + h] * fc2w[((size_t)n * 64 + h) * 3 + o];
        s_o[b * 3 + o] = acc;
    } else if (tid >= 32 && tid < 48) {
        const int q = tid - 32, b = q >> 1, which = q & 1;
        float s = 0.f;
        const int base = 64 + which * 64;
        #pragma unroll 8
        for (int d = 0; d < 64; d++) {
            const float v = s_in[(base + d) * 12 + b];
            s += v * v;
        }
        s_norm[b * 2 + which] = fmaxf(sqrtf(s), 1e-8f);
    }
    __syncthreads();

    // ---- finalize eff_* and init state ----
    {
        const int b = tid >> 6, d = tid & 63;
        const float mod_lr = sigf(mll[0]);
        const float gp = tanhf(s_o[b * 3 + 0]);
        const float gk = tanhf(s_o[b * 3 + 1]);
        const float dm = s_o[b * 3 + 2];
        const float tpv = s_in[(64 + d) * 12 + b];
        const float tkv = s_in[(128 + d) * 12 + b];
        const size_t off = ((size_t)b * NN + n) * DD + d;
        g_ep[off] = prim[(size_t)n * DD + d] + mod_lr * gp * (tpv / s_norm[b * 2 + 0]);
        g_ek[off] = keyp[(size_t)n * DD + d] + mod_lr * gk * (tkv / s_norm[b * 2 + 1]);
        g_h [off] = s_in[d * 12 + b];
        g_pm[0][off] = pm_in[off];
        if (d == 0) g_ed[(size_t)b * NN + n] = sigf(dlog[n] + dm);
    }
}

// =============================================================================
// Kernel B: one scan update.  One CTA per neuron n, 8 warps = 8 batches.
// k processed in 2 chunks of 16 -> msg smem halved -> 5 CTAs/SM (40 warps).
// =============================================================================
#define MROW   66                       // pad: conflict-free for both phases
#define MSGF   (16 * MROW)              // floats per warp's msg buffer
#define SMEM_B ((8 * MSGF + 2048 + 256 + 512) * 4 + 32 * 4)   // ~44.3 KB

__global__ void __launch_bounds__(256, 5) stepk(
    int parity, int t0,
    const float* __restrict__ cc, const float* __restrict__ bw,
    const float* __restrict__ gw, const int* __restrict__ conn,
    float* __restrict__ out)
{
    extern __shared__ float sm[];
    float* s_msg = sm;                         // 8 * 16 * 66
    float* s_bw  = sm + 8 * MSGF;              // 32 * 64
    float* s_gw  = s_bw + 2048;                // 4 * 64
    float* s_key = s_gw + 256;                 // 8 * 64
    int*   s_idx = (int*)(s_key + 512);        // 32

    const int n   = blockIdx.x;
    const int tid = threadIdx.x;
    const int b   = tid >> 5;
    const int l   = tid & 31;

    const float* pm_in  = g_pm[parity];
    float*       pm_out = g_pm[parity ^ 1];

    for (int i = tid; i < 2048; i += 256) s_bw[i] = bw[(size_t)n * 2048 + i];
    if (tid < 256) s_gw[tid] = gw[(size_t)n * 256 + tid];
    if (tid < 32)  s_idx[tid] = conn[(size_t)n * KK + tid];
    for (int i = tid; i < 512; i += 256) {
        const int bb = i >> 6, dd = i & 63;
        s_key[i] = g_ek[((size_t)bb * NN + n) * DD + dd];
    }
    __syncthreads();

    float* M = s_msg + b * MSGF;
    const float* pmb = pm_in + (size_t)b * NN * DD;

    float acc[4][2] = {{0,0},{0,0},{0,0},{0,0}};

    #pragma unroll
    for (int cch = 0; cch < 2; cch++) {
        // ---- gather 16 neighbor messages (coalesced L2 loads) ----
        #pragma unroll
        for (int kk = 0; kk < 16; kk++) {
            const int src = s_idx[cch * 16 + kk];
            M[kk * MROW + l]      = __ldg(&pmb[src * DD + l]);
            M[kk * MROW + 32 + l] = __ldg(&pmb[src * DD + 32 + l]);
        }
        __syncwarp();

        // ---- sims: half-warp, lane l<16 computes dot(eff_key, msg_l) ----
        float w = 0.f;
        if (l < 16) {
            const float2* mk = (const float2*)(M + l * MROW);
            const float2* kf = (const float2*)(s_key + b * 64);
            float s = 0.f;
            #pragma unroll
            for (int q = 0; q < 32; q++) {
                const float2 kv = kf[q];
                const float2 mv = mk[q];
                s += kv.x * mv.x + kv.y * mv.y;
            }
            w = sigf(s);
        }
        __syncwarp();

        // ---- weighted + branch partial sums: lane l owns d=l and d=l+32 ----
        #pragma unroll
        for (int kk = 0; kk < 16; kk++) {
            const int k = cch * 16 + kk;
            const float wk = __shfl_sync(0xffffffffu, w, kk);
            const float m0 = M[kk * MROW + l],    m1 = M[kk * MROW + 32 + l];
            const float w0 = s_bw[k * 64 + l],    w1 = s_bw[k * 64 + 32 + l];
            acc[k >> 3][0] += (wk * m0) * w0;
            acc[k >> 3][1] += (wk * m1) * w1;
        }
        __syncwarp();   // before next chunk overwrites M
    }

    // ---- branch tanh -> group sum -> group tanh (ng=1, mean = identity) ----
    float r0 = 0.f, r1 = 0.f;
    #pragma unroll
    for (int nb = 0; nb < 4; nb++) {
        r0 += tanhf(acc[nb][0]) * s_gw[nb * 64 + l];
        r1 += tanhf(acc[nb][1]) * s_gw[nb * 64 + 32 + l];
    }
    r0 = tanhf(r0);
    r1 = tanhf(r1);

    if (n < C_) {   // cc injection on first C neurons
        const size_t cco = (((size_t)b * T_ + t0) * C_ + n) * DD;
        r0 += cc[cco + l];
        r1 += cc[cco + 32 + l];
    }

    // ---- h / message update ----
    const size_t off = ((size_t)b * NN + n) * DD;
    const float ed = g_ed[(size_t)b * NN + n];
    const float h0 = g_h[off + l], h1 = g_h[off + 32 + l];
    const float nh0 = ed * h0 + (1.f - ed) * r0;
    const float nh1 = ed * h1 + (1.f - ed) * r1;
    g_h[off + l]      = nh0;
    g_h[off + 32 + l] = nh1;
    const float p0 = tanhf(nh0 * g_ep[off + l]);
    const float p1 = tanhf(nh1 * g_ep[off + 32 + l]);
    pm_out[off + l]      = p0;
    pm_out[off + 32 + l] = p1;

    if (n < C_) {   // emit the 4 timesteps this update covers
        #pragma unroll
        for (int tt = 0; tt < 4; tt++) {
            const size_t oo = (((size_t)b * T_ + t0 + tt) * C_ + n) * DD;
            out[oo + l]      = p0;
            out[oo + 32 + l] = p1;
        }
    }
}

// =============================================================================
extern "C" void kernel_launch(void* const* d_in, const int* in_sizes, int n_in,
                              void* d_out, int out_size)
{
    const float* cc    = (const float*)d_in[0];
    const float* h_in  = (const float*)d_in[1];
    const float* pm_in = (const float*)d_in[2];
    const float* tp    = (const float*)d_in[3];
    const float* tk    = (const float*)d_in[4];
    const float* prim  = (const float*)d_in[5];
    const float* keyp  = (const float*)d_in[6];
    const float* dlog  = (const float*)d_in[7];
    const float* bw    = (const float*)d_in[8];
    const float* gw    = (const float*)d_in[9];
    const float* fc1w  = (const float*)d_in[10];
    const float* fc1b  = (const float*)d_in[11];
    const float* fc2w  = (const float*)d_in[12];
    const float* fc2b  = (const float*)d_in[13];
    const float* mll   = (const float*)d_in[14];
    const int*   conn  = (const int*)d_in[15];
    float* out = (float*)d_out;

    cudaFuncSetAttribute(stepk, cudaFuncAttributeMaxDynamicSharedMemorySize, SMEM_B);

    modk<<<NN, 512>>>(h_in, pm_in, tp, tk, prim, keyp, dlog,
                      fc1w, fc1b, fc2w, fc2b, mll);

    // stride = 4 (fixed by setup): updates at t = 0,4,...,28; output replicated x4
    for (int u = 0; u < 8; u++) {
        stepk<<<NN, 256, SMEM_B>>>(u & 1, 4 * u, cc, bw, gw, conn, out);
    }
}

// round 3
// speedup vs baseline: 3.2565x; 1.8817x over previous
#include <cuda_runtime.h>
#include <math.h>

#define BS   8
#define T_   32
#define C_   64
#define NN   4096
#define KK   32
#define DD   64
#define HH   64
#define FIN  320   // 5*D

// ---------------- persistent scratch (no allocation allowed) ----------------
__device__ float g_pm[2][BS * NN * DD];   // double-buffered messages
__device__ float g_h [BS * NN * DD];      // hidden state (in-place per update)
__device__ float g_ep[BS * NN * DD];      // eff_prim
__device__ float g_ek[BS * NN * DD];      // eff_key
__device__ float g_ed[BS * NN];           // eff_decay (scalar per b,n)

__device__ __forceinline__ float sigf(float x) { return 1.f / (1.f + __expf(-x)); }

// =============================================================================
// Kernel A: modulator MLP + state init.  One CTA per neuron n, 512 threads.
// =============================================================================
__global__ void __launch_bounds__(512) modk(
    const float* __restrict__ h_in, const float* __restrict__ pm_in,
    const float* __restrict__ tp,   const float* __restrict__ tk,
    const float* __restrict__ prim, const float* __restrict__ keyp,
    const float* __restrict__ dlog, const float* __restrict__ fc1w,
    const float* __restrict__ fc1b, const float* __restrict__ fc2w,
    const float* __restrict__ fc2b, const float* __restrict__ mll)
{
    const int n   = blockIdx.x;
    const int tid = threadIdx.x;

    __shared__ __align__(16) float s_in[FIN * 12];      // [j][b] pad 12 (float4-friendly)
    __shared__ float s_part[8 * 8 * 64];                // [seg][b][h]
    __shared__ float s_x[8 * 64];                       // tanh(fc1) activations
    __shared__ float s_o[24];                           // fc2 outputs [b][3]
    __shared__ float s_norm[16];                        // [b][{prim,key}]

    // ---- stage mod_input transposed: s_in[j*12 + b] ----
    for (int idx = tid; idx < BS * FIN; idx += 512) {
        const int b = idx / FIN, j = idx % FIN;
        float v;
        if      (j <  64) v = h_in[((size_t)b * NN + n) * DD + j];
        else if (j < 128) v = tp  [((size_t)b * NN + n) * DD + j - 64];
        else if (j < 192) v = tk  [((size_t)b * NN + n) * DD + j - 128];
        else if (j < 256) v = prim[(size_t)n * DD + j - 192];
        else              v = keyp[(size_t)n * DD + j - 256];
        s_in[j * 12 + b] = v;
    }
    __syncthreads();

    // ---- fc1: thread (seg,h) covers j in [seg*40, seg*40+40) for ALL 8 batches ----
    {
        const int seg = tid >> 6, hh = tid & 63;
        float a0=0,a1=0,a2=0,a3=0,a4=0,a5=0,a6=0,a7=0;
        const float* W = fc1w + (size_t)n * FIN * HH + hh;
        const int j0 = seg * 40;
        #pragma unroll 8
        for (int jj = 0; jj < 40; jj++) {
            const int j = j0 + jj;
            const float w = W[(size_t)j * HH];
            const float4 i0 = *(const float4*)&s_in[j * 12];
            const float4 i1 = *(const float4*)&s_in[j * 12 + 4];
            a0 += w * i0.x; a1 += w * i0.y; a2 += w * i0.z; a3 += w * i0.w;
            a4 += w * i1.x; a5 += w * i1.y; a6 += w * i1.z; a7 += w * i1.w;
        }
        float acc[8] = {a0,a1,a2,a3,a4,a5,a6,a7};
        #pragma unroll
        for (int b = 0; b < 8; b++)
            s_part[(seg * 8 + b) * 64 + hh] = acc[b];
    }
    __syncthreads();

    // ---- reduce segments, bias, tanh ----
    {
        const int b = tid >> 6, h = tid & 63;
        float s = 0.f;
        #pragma unroll
        for (int seg = 0; seg < 8; seg++) s += s_part[(seg * 8 + b) * 64 + h];
        s_x[b * 64 + h] = tanhf(s + fc1b[(size_t)n * HH + h]);
    }
    __syncthreads();

    // ---- fc2 (24 threads) + trace norms (threads 32..47) ----
    if (tid < 24) {
        const int b = tid / 3, o = tid % 3;
        float acc = fc2b[(size_t)n * 3 + o];
        #pragma unroll 8
        for (int h = 0; h < 64; h++)
            acc += s_x[b * 64 + h] * fc2w[((size_t)n * 64 + h) * 3 + o];
        s_o[b * 3 + o] = acc;
    } else if (tid >= 32 && tid < 48) {
        const int q = tid - 32, b = q >> 1, which = q & 1;
        float s = 0.f;
        const int base = 64 + which * 64;
        #pragma unroll 8
        for (int d = 0; d < 64; d++) {
            const float v = s_in[(base + d) * 12 + b];
            s += v * v;
        }
        s_norm[b * 2 + which] = fmaxf(sqrtf(s), 1e-8f);
    }
    __syncthreads();

    // ---- finalize eff_* and init state ----
    {
        const int b = tid >> 6, d = tid & 63;
        const float mod_lr = sigf(mll[0]);
        const float gp = tanhf(s_o[b * 3 + 0]);
        const float gk = tanhf(s_o[b * 3 + 1]);
        const float dm = s_o[b * 3 + 2];
        const float tpv = s_in[(64 + d) * 12 + b];
        const float tkv = s_in[(128 + d) * 12 + b];
        const size_t off = ((size_t)b * NN + n) * DD + d;
        g_ep[off] = prim[(size_t)n * DD + d] + mod_lr * gp * (tpv / s_norm[b * 2 + 0]);
        g_ek[off] = keyp[(size_t)n * DD + d] + mod_lr * gk * (tkv / s_norm[b * 2 + 1]);
        g_h [off] = s_in[d * 12 + b];
        g_pm[0][off] = pm_in[off];
        if (d == 0) g_ed[(size_t)b * NN + n] = sigf(dlog[n] + dm);
    }
}

// =============================================================================
// Kernel B: one scan update.  One CTA per neuron n, 8 warps = 8 batches.
// Messages live entirely in registers (lane l owns d=2l,2l+1); sims via a
// 5-stage butterfly multi-reduce (8 sims per chunk).  smem = 9.3 KB static.
// =============================================================================
__global__ void __launch_bounds__(256, 4) stepk(
    int parity, int t0,
    const float* __restrict__ cc, const float* __restrict__ bw,
    const float* __restrict__ gw, const int* __restrict__ conn,
    float* __restrict__ out)
{
    __shared__ float s_bw[2048];   // [k][d]
    __shared__ float s_gw[256];    // [nb][d]
    __shared__ int   s_idx[32];

    const int n   = blockIdx.x;
    const int tid = threadIdx.x;
    const int b   = tid >> 5;
    const int l   = tid & 31;

    const float* pm_in  = g_pm[parity];
    float*       pm_out = g_pm[parity ^ 1];

    #pragma unroll
    for (int i = 0; i < 8; i++) s_bw[tid + 256 * i] = bw[(size_t)n * 2048 + tid + 256 * i];
    s_gw[tid] = gw[(size_t)n * 256 + tid];
    if (tid < 32) s_idx[tid] = conn[(size_t)n * KK + tid];

    const size_t off = ((size_t)b * NN + n) * DD;
    const float2 key = *(const float2*)&g_ek[off + 2 * l];
    __syncthreads();

    const float* pmb = pm_in + (size_t)b * NN * DD;
    float2 accv[4];

    #pragma unroll
    for (int c = 0; c < 4; c++) {
        // ---- gather 8 messages: lane l holds d=2l, 2l+1 of each ----
        float2 m[8];
        #pragma unroll
        for (int kk = 0; kk < 8; kk++) {
            const int src = s_idx[c * 8 + kk];
            m[kk] = __ldg((const float2*)&pmb[src * DD + 2 * l]);
        }

        // ---- per-lane sim partials ----
        float v[8];
        #pragma unroll
        for (int kk = 0; kk < 8; kk++)
            v[kk] = key.x * m[kk].x + key.y * m[kk].y;

        // ---- butterfly multi-reduce: 8 sums over 32 lanes in 5 stages ----
        {
            const bool h16 = (l & 16);
            #pragma unroll
            for (int i = 0; i < 4; i++) {
                const float keep = h16 ? v[4 + i] : v[i];
                const float send = h16 ? v[i]     : v[4 + i];
                v[i] = keep + __shfl_xor_sync(0xffffffffu, send, 16);
            }
            const bool h8 = (l & 8);
            #pragma unroll
            for (int i = 0; i < 2; i++) {
                const float keep = h8 ? v[2 + i] : v[i];
                const float send = h8 ? v[i]     : v[2 + i];
                v[i] = keep + __shfl_xor_sync(0xffffffffu, send, 8);
            }
            const bool h4 = (l & 4);
            {
                const float keep = h4 ? v[1] : v[0];
                const float send = h4 ? v[0] : v[1];
                v[0] = keep + __shfl_xor_sync(0xffffffffu, send, 4);
            }
            v[0] += __shfl_xor_sync(0xffffffffu, v[0], 2);
            v[0] += __shfl_xor_sync(0xffffffffu, v[0], 1);
        }
        // lane l now holds sim for kk = (l >> 2) & 7
        const float w = sigf(v[0]);

        // ---- weighted + branch partial sums ----
        float ax = 0.f, ay = 0.f;
        #pragma unroll
        for (int kk = 0; kk < 8; kk++) {
            const float wk = __shfl_sync(0xffffffffu, w, kk << 2);
            const float2 bwv = *(const float2*)&s_bw[(c * 8 + kk) * 64 + 2 * l];
            ax += (wk * m[kk].x) * bwv.x;
            ay += (wk * m[kk].y) * bwv.y;
        }
        accv[c].x = ax; accv[c].y = ay;
    }

    // ---- branch tanh -> group sum -> group tanh (ng=1, mean = identity) ----
    float r0 = 0.f, r1 = 0.f;
    #pragma unroll
    for (int nb = 0; nb < 4; nb++) {
        const float2 gwv = *(const float2*)&s_gw[nb * 64 + 2 * l];
        r0 += tanhf(accv[nb].x) * gwv.x;
        r1 += tanhf(accv[nb].y) * gwv.y;
    }
    r0 = tanhf(r0);
    r1 = tanhf(r1);

    if (n < C_) {   // cc injection on first C neurons
        const float2 ccv = *(const float2*)&cc[(((size_t)b * T_ + t0) * C_ + n) * DD + 2 * l];
        r0 += ccv.x;
        r1 += ccv.y;
    }

    // ---- h / message update ----
    const float ed = g_ed[(size_t)b * NN + n];
    const float2 h = *(const float2*)&g_h[off + 2 * l];
    const float nh0 = ed * h.x + (1.f - ed) * r0;
    const float nh1 = ed * h.y + (1.f - ed) * r1;
    *(float2*)&g_h[off + 2 * l] = make_float2(nh0, nh1);
    const float2 ep = *(const float2*)&g_ep[off + 2 * l];
    const float p0 = tanhf(nh0 * ep.x);
    const float p1 = tanhf(nh1 * ep.y);
    *(float2*)&pm_out[off + 2 * l] = make_float2(p0, p1);

    if (n < C_) {   // emit the 4 timesteps this update covers
        #pragma unroll
        for (int tt = 0; tt < 4; tt++) {
            const size_t oo = (((size_t)b * T_ + t0 + tt) * C_ + n) * DD + 2 * l;
            *(float2*)&out[oo] = make_float2(p0, p1);
        }
    }
}

// =============================================================================
extern "C" void kernel_launch(void* const* d_in, const int* in_sizes, int n_in,
                              void* d_out, int out_size)
{
    const float* cc    = (const float*)d_in[0];
    const float* h_in  = (const float*)d_in[1];
    const float* pm_in = (const float*)d_in[2];
    const float* tp    = (const float*)d_in[3];
    const float* tk    = (const float*)d_in[4];
    const float* prim  = (const float*)d_in[5];
    const float* keyp  = (const float*)d_in[6];
    const float* dlog  = (const float*)d_in[7];
    const float* bw    = (const float*)d_in[8];
    const float* gw    = (const float*)d_in[9];
    const float* fc1w  = (const float*)d_in[10];
    const float* fc1b  = (const float*)d_in[11];
    const float* fc2w  = (const float*)d_in[12];
    const float* fc2b  = (const float*)d_in[13];
    const float* mll   = (const float*)d_in[14];
    const int*   conn  = (const int*)d_in[15];
    float* out = (float*)d_out;

    modk<<<NN, 512>>>(h_in, pm_in, tp, tk, prim, keyp, dlog,
                      fc1w, fc1b, fc2w, fc2b, mll);

    // stride = 4 (fixed by setup): updates at t = 0,4,...,28; output replicated x4
    for (int u = 0; u < 8; u++) {
        stepk<<<NN, 256>>>(u & 1, 4 * u, cc, bw, gw, conn, out);
    }
}